// round 1
// baseline (speedup 1.0000x reference)
#include <cuda_runtime.h>
#include <cuda_bf16.h>
#include <math.h>

// Problem constants (shapes are fixed by the dataset; buffers sized with margin)
#define Hh 256
#define NMAX 262144
#define BMAX 4096

// ---------------- device scratch (no allocations allowed) ----------------
__device__ float d_e[NMAX];                 // per-node attention scratch
__device__ int   d_starts[BMAX + 1];        // graph segment starts
__device__ int   d_is64;                    // graph_id dtype flag
__device__ float d_X0[BMAX * 768];          // [q_star(512) | h0(256)]  layer0 GEMM input
__device__ float d_X1[BMAX * 512];          // [h0(256) | h1(256)]      layer1 GEMM input; q = X1[:,256:512]
__device__ float d_gates[BMAX * 1024];      // GEMM output (4H gates)
__device__ float d_c0[BMAX * 256];
__device__ float d_c1[BMAX * 256];
__device__ float d_W0[1024 * 768];          // [Wih0 | Whh0]
__device__ float d_W1[1024 * 512];          // [Wih1 | Whh1]
__device__ float d_b0[1024];                // bih0+bhh0
__device__ float d_b1[1024];

// ---------------- graph_id dtype detection ----------------
__global__ void detect_kernel(const int* p, int N) {
    // If data is int64 (little-endian, values < 2^31), every odd int32 word is 0.
    // If data is int32, odd words near the end hold graph ids ~B-1 (nonzero).
    int z = 1;
    for (int j = 0; j < 8; j++) {
        int idx = N - 1 - 2 * j;
        if (idx < 1) break;
        if ((idx & 1) == 0) idx--;
        if (idx >= 1 && p[idx] != 0) z = 0;
    }
    d_is64 = z;
}

__device__ __forceinline__ int get_gid(const void* p, int i) {
    if (d_is64) return (int)((const long long*)p)[i];
    return ((const int*)p)[i];
}

// ---------------- segment starts via binary search (graph_id sorted) ----------------
__global__ void starts_kernel(const void* gid, int N, int B) {
    int g = blockIdx.x * blockDim.x + threadIdx.x;
    if (g > B) return;
    int lo = 0, hi = N;
    while (lo < hi) {
        int mid = (lo + hi) >> 1;
        if (get_gid(gid, mid) < g) lo = mid + 1; else hi = mid;
    }
    d_starts[g] = lo;
}

// ---------------- pack concatenated weights + summed biases ----------------
__global__ void pack_kernel(const float* __restrict__ Wih0, const float* __restrict__ Whh0,
                            const float* __restrict__ bih0, const float* __restrict__ bhh0,
                            const float* __restrict__ Wih1, const float* __restrict__ Whh1,
                            const float* __restrict__ bih1, const float* __restrict__ bhh1) {
    int i = blockIdx.x * blockDim.x + threadIdx.x;
    if (i < 1024 * 768) {
        int j = i / 768, k = i % 768;
        d_W0[i] = (k < 512) ? Wih0[j * 512 + k] : Whh0[j * 256 + (k - 512)];
    }
    if (i < 1024 * 512) {
        int j = i / 512, k = i % 512;
        d_W1[i] = (k < 256) ? Wih1[j * 256 + k] : Whh1[j * 256 + (k - 256)];
    }
    if (i < 1024) {
        d_b0[i] = bih0[i] + bhh0[i];
        d_b1[i] = bih1[i] + bhh1[i];
    }
}

// ---------------- zero-init state ----------------
__global__ void init_kernel(int B) {
    int i = blockIdx.x * blockDim.x + threadIdx.x;
    int n0 = B * 768, n1 = B * 512, n2 = B * 256;
    if (i < n0) { d_X0[i] = 0.f; return; }
    i -= n0;
    if (i < n1) { d_X1[i] = 0.f; return; }
    i -= n1;
    if (i < n2) { d_c0[i] = 0.f; return; }
    i -= n2;
    if (i < n2) { d_c1[i] = 0.f; return; }
}

// ---------------- attention + segment softmax + weighted readout ----------------
// One CTA per graph. q = d_X1[g, 256:512]. Writes q_star = [q | r] either into
// d_X0 (stride 768, feeding the layer0 GEMM) or into d_out (stride 512, final).
__global__ void attention_kernel(const float* __restrict__ nodes,
                                 float* __restrict__ dout, int final_iter) {
    int g = blockIdx.x;
    int s = d_starts[g], en = d_starts[g + 1];
    __shared__ float qs[256];
    __shared__ float red[8];
    __shared__ float s_max, s_inv;
    int tid = threadIdx.x, lane = tid & 31, w = tid >> 5;

    qs[tid] = d_X1[(size_t)g * 512 + 256 + tid];
    __syncthreads();

    // phase 1: e[n] = <nodes[n], q>, track block max
    float lmax = -3.4e38f;
    for (int n = s + w; n < en; n += 8) {
        const float* row = nodes + (size_t)n * 256;
        float d = 0.f;
        #pragma unroll
        for (int k = 0; k < 8; k++) d = fmaf(row[lane + 32 * k], qs[lane + 32 * k], d);
        #pragma unroll
        for (int o = 16; o; o >>= 1) d += __shfl_xor_sync(0xffffffffu, d, o);
        if (lane == 0) d_e[n] = d;
        lmax = fmaxf(lmax, d);
    }
    if (lane == 0) red[w] = lmax;
    __syncthreads();
    if (tid == 0) {
        float m = red[0];
        #pragma unroll
        for (int i = 1; i < 8; i++) m = fmaxf(m, red[i]);
        s_max = m;
    }
    __syncthreads();
    float gm = s_max;

    // phase 2: exp and sum
    float lsum = 0.f;
    for (int n = s + tid; n < en; n += 256) {
        float ex = expf(d_e[n] - gm);
        d_e[n] = ex;
        lsum += ex;
    }
    #pragma unroll
    for (int o = 16; o; o >>= 1) lsum += __shfl_xor_sync(0xffffffffu, lsum, o);
    if (lane == 0) red[w] = lsum;
    __syncthreads();
    if (tid == 0) {
        float sd = 0.f;
        #pragma unroll
        for (int i = 0; i < 8; i++) sd += red[i];
        s_inv = (sd > 0.f) ? 1.f / sd : 0.f;
    }
    __syncthreads();
    float inv = s_inv;

    // phase 3: r[t] = sum_n a_n * nodes[n][t]  (thread-per-dim, coalesced rows)
    float a0 = 0.f, a1 = 0.f, a2 = 0.f, a3 = 0.f;
    int n = s;
    for (; n + 3 < en; n += 4) {
        a0 = fmaf(d_e[n + 0], nodes[(size_t)(n + 0) * 256 + tid], a0);
        a1 = fmaf(d_e[n + 1], nodes[(size_t)(n + 1) * 256 + tid], a1);
        a2 = fmaf(d_e[n + 2], nodes[(size_t)(n + 2) * 256 + tid], a2);
        a3 = fmaf(d_e[n + 3], nodes[(size_t)(n + 3) * 256 + tid], a3);
    }
    for (; n < en; n++) a0 = fmaf(d_e[n], nodes[(size_t)n * 256 + tid], a0);
    float acc = ((a0 + a1) + (a2 + a3)) * inv;

    float* out; int stride;
    if (final_iter) { out = dout; stride = 512; }
    else            { out = d_X0; stride = 768; }
    out[(size_t)g * stride + tid] = qs[tid];
    out[(size_t)g * stride + 256 + tid] = acc;
}

// ---------------- fp32 SGEMM (NT): gates[M,1024] = X[M,K] * W[1024,K]^T ----------------
// 128x128 block tile, BK=8, 256 threads, 8x8 micro-tile per thread.
__global__ __launch_bounds__(256) void sgemm_gates(int layer, int M) {
    const float* __restrict__ A = (layer == 0) ? d_X0 : d_X1;
    const float* __restrict__ W = (layer == 0) ? d_W0 : d_W1;
    const int K = (layer == 0) ? 768 : 512;

    __shared__ float As[8][128];
    __shared__ float Bs[8][128];

    int tid = threadIdx.x;
    int lr = tid >> 1;            // 0..127
    int lk = (tid & 1) * 4;       // 0 or 4
    int arow = blockIdx.y * 128 + lr;
    int brow = blockIdx.x * 128 + lr;   // < 1024 always
    bool avalid = (arow < M);
    const float* Ap = A + (size_t)(avalid ? arow : 0) * K + lk;
    const float* Bp = W + (size_t)brow * K + lk;

    int tx = tid & 15, ty = tid >> 4;
    float acc[8][8];
    #pragma unroll
    for (int i = 0; i < 8; i++)
        #pragma unroll
        for (int j = 0; j < 8; j++) acc[i][j] = 0.f;

    for (int k0 = 0; k0 < K; k0 += 8) {
        float4 a4 = avalid ? *(const float4*)(Ap + k0) : make_float4(0.f, 0.f, 0.f, 0.f);
        float4 b4 = *(const float4*)(Bp + k0);
        __syncthreads();
        As[lk + 0][lr] = a4.x; As[lk + 1][lr] = a4.y; As[lk + 2][lr] = a4.z; As[lk + 3][lr] = a4.w;
        Bs[lk + 0][lr] = b4.x; Bs[lk + 1][lr] = b4.y; Bs[lk + 2][lr] = b4.z; Bs[lk + 3][lr] = b4.w;
        __syncthreads();
        #pragma unroll
        for (int kk = 0; kk < 8; kk++) {
            float ar[8], br[8];
            #pragma unroll
            for (int i = 0; i < 8; i++) ar[i] = As[kk][ty * 8 + i];
            #pragma unroll
            for (int j = 0; j < 8; j++) br[j] = Bs[kk][tx * 8 + j];
            #pragma unroll
            for (int i = 0; i < 8; i++)
                #pragma unroll
                for (int j = 0; j < 8; j++) acc[i][j] = fmaf(ar[i], br[j], acc[i][j]);
        }
    }

    #pragma unroll
    for (int i = 0; i < 8; i++) {
        int r = blockIdx.y * 128 + ty * 8 + i;
        if (r < M) {
            float* Cp = d_gates + (size_t)r * 1024 + blockIdx.x * 128 + tx * 8;
            *(float4*)(Cp + 0) = make_float4(acc[i][0], acc[i][1], acc[i][2], acc[i][3]);
            *(float4*)(Cp + 4) = make_float4(acc[i][4], acc[i][5], acc[i][6], acc[i][7]);
        }
    }
}

// ---------------- LSTM pointwise: gates -> (h, c) ----------------
// layer 0: h0 -> X0[:,512:768] and X1[:,0:256]; layer 1: h1 -> X1[:,256:512]
__global__ void lstm_act_kernel(int layer, int B) {
    int idx = blockIdx.x * blockDim.x + threadIdx.x;
    if (idx >= B * 256) return;
    int b = idx >> 8, t = idx & 255;
    const float* gr = d_gates + (size_t)b * 1024;
    const float* bs = (layer == 0) ? d_b0 : d_b1;
    float* c = (layer == 0) ? d_c0 : d_c1;

    float gi = gr[t]       + bs[t];
    float gf = gr[t + 256] + bs[t + 256];
    float gg = gr[t + 512] + bs[t + 512];
    float go = gr[t + 768] + bs[t + 768];

    float si = 1.f / (1.f + expf(-gi));
    float sf = 1.f / (1.f + expf(-gf));
    float tg = tanhf(gg);
    float so = 1.f / (1.f + expf(-go));

    float cn = sf * c[idx] + si * tg;
    c[idx] = cn;
    float hn = so * tanhf(cn);

    if (layer == 0) {
        d_X0[(size_t)b * 768 + 512 + t] = hn;
        d_X1[(size_t)b * 512 + t]       = hn;
    } else {
        d_X1[(size_t)b * 512 + 256 + t] = hn;
    }
}

// ---------------- host launcher ----------------
extern "C" void kernel_launch(void* const* d_in, const int* in_sizes, int n_in,
                              void* d_out, int out_size) {
    const float* nodes = (const float*)d_in[0];
    const void*  gid   = d_in[1];
    int N = in_sizes[1];

    // num_graphs may or may not be passed as a 1-element input
    int wbase = (in_sizes[2] == 1) ? 3 : 2;
    const float* Wih0 = (const float*)d_in[wbase + 0];
    const float* Whh0 = (const float*)d_in[wbase + 1];
    const float* bih0 = (const float*)d_in[wbase + 2];
    const float* bhh0 = (const float*)d_in[wbase + 3];
    const float* Wih1 = (const float*)d_in[wbase + 4];
    const float* Whh1 = (const float*)d_in[wbase + 5];
    const float* bih1 = (const float*)d_in[wbase + 6];
    const float* bhh1 = (const float*)d_in[wbase + 7];

    int B = out_size / (2 * Hh);   // output is [B, 2H]
    float* out = (float*)d_out;

    detect_kernel<<<1, 1>>>((const int*)gid, N);
    starts_kernel<<<(B + 1 + 255) / 256, 256>>>(gid, N, B);
    pack_kernel<<<(1024 * 768 + 255) / 256, 256>>>(Wih0, Whh0, bih0, bhh0,
                                                   Wih1, Whh1, bih1, bhh1);
    init_kernel<<<(B * 1792 + 255) / 256, 256>>>(B);

    dim3 gemm_grid(1024 / 128, (B + 127) / 128);
    const int M_ITERS = 6;
    for (int i = 0; i < M_ITERS; i++) {
        int final_iter = (i == M_ITERS - 1) ? 1 : 0;
        attention_kernel<<<B, 256>>>(nodes, out, final_iter);
        if (!final_iter) {
            sgemm_gates<<<gemm_grid, 256>>>(0, B);
            lstm_act_kernel<<<(B * 256 + 255) / 256, 256>>>(0, B);
            sgemm_gates<<<gemm_grid, 256>>>(1, B);
            lstm_act_kernel<<<(B * 256 + 255) / 256, 256>>>(1, B);
        }
    }
}

// round 3
// speedup vs baseline: 2.0069x; 2.0069x over previous
#include <cuda_runtime.h>
#include <cuda_bf16.h>
#include <math.h>
#include <stdint.h>

#define Hh 256
#define NMAX 262144
#define BMAX 4096

// ---------------- device scratch (no allocations allowed) ----------------
__device__ float d_e[NMAX];
__device__ int   d_starts[BMAX + 1];
__device__ int   d_is64;
__device__ float d_q[BMAX * 256];            // q = h1 (fp32, for attention)
__device__ float d_gates[BMAX * 1024];
__device__ float d_c0[BMAX * 256];
__device__ float d_c1[BMAX * 256];
// bf16 split operands for GEMMs
__device__ __nv_bfloat16 d_X0h[BMAX * 768], d_X0l[BMAX * 768];   // [q_star(512)|h0(256)]
__device__ __nv_bfloat16 d_X1h[BMAX * 512], d_X1l[BMAX * 512];   // [h0(256)|h1(256)]
__device__ __nv_bfloat16 d_W0h[1024 * 768], d_W0l[1024 * 768];   // [Wih0|Whh0]
__device__ __nv_bfloat16 d_W1h[1024 * 512], d_W1l[1024 * 512];   // [Wih1|Whh1]
__device__ float d_b0[1024], d_b1[1024];

// ---------------- small helpers ----------------
__device__ __forceinline__ uint32_t smem_u32(const void* p) {
    uint32_t a;
    asm("{ .reg .u64 t; cvta.to.shared.u64 t, %1; cvt.u32.u64 %0, t; }" : "=r"(a) : "l"(p));
    return a;
}
__device__ __forceinline__ void cp16(uint32_t dst, const void* src) {
    asm volatile("cp.async.cg.shared.global [%0], [%1], 16;" :: "r"(dst), "l"(src));
}
#define CP_COMMIT() asm volatile("cp.async.commit_group;" ::: "memory")
#define CP_WAIT1()  asm volatile("cp.async.wait_group 1;" ::: "memory")
#define CP_WAIT0()  asm volatile("cp.async.wait_group 0;" ::: "memory")

__device__ __forceinline__ void ldsm4(uint32_t* r, uint32_t addr) {
    asm volatile("ldmatrix.sync.aligned.m8n8.x4.shared.b16 {%0,%1,%2,%3}, [%4];"
                 : "=r"(r[0]), "=r"(r[1]), "=r"(r[2]), "=r"(r[3]) : "r"(addr));
}
__device__ __forceinline__ void mma16816(float* c, const uint32_t* a, const uint32_t* b) {
    asm volatile(
        "mma.sync.aligned.m16n8k16.row.col.f32.bf16.bf16.f32 "
        "{%0,%1,%2,%3},{%4,%5,%6,%7},{%8,%9},{%0,%1,%2,%3};"
        : "+f"(c[0]), "+f"(c[1]), "+f"(c[2]), "+f"(c[3])
        : "r"(a[0]), "r"(a[1]), "r"(a[2]), "r"(a[3]), "r"(b[0]), "r"(b[1]));
}
__device__ __forceinline__ void split_bf16(float x, __nv_bfloat16& h, __nv_bfloat16& l) {
    h = __float2bfloat16(x);
    l = __float2bfloat16(x - __bfloat162float(h));
}

// ---------------- graph_id dtype detection ----------------
__global__ void detect_kernel(const int* p, int N) {
    int z = 1;
    for (int j = 0; j < 8; j++) {
        int idx = N - 1 - 2 * j;
        if (idx < 1) break;
        if ((idx & 1) == 0) idx--;
        if (idx >= 1 && p[idx] != 0) z = 0;
    }
    d_is64 = z;
}
__device__ __forceinline__ int get_gid(const void* p, int i) {
    if (d_is64) return (int)((const long long*)p)[i];
    return ((const int*)p)[i];
}
__global__ void starts_kernel(const void* gid, int N, int B) {
    int g = blockIdx.x * blockDim.x + threadIdx.x;
    if (g > B) return;
    int lo = 0, hi = N;
    while (lo < hi) {
        int mid = (lo + hi) >> 1;
        if (get_gid(gid, mid) < g) lo = mid + 1; else hi = mid;
    }
    d_starts[g] = lo;
}

// ---------------- pack weights (bf16 split) + summed biases ----------------
__global__ void pack_kernel(const float* __restrict__ Wih0, const float* __restrict__ Whh0,
                            const float* __restrict__ bih0, const float* __restrict__ bhh0,
                            const float* __restrict__ Wih1, const float* __restrict__ Whh1,
                            const float* __restrict__ bih1, const float* __restrict__ bhh1) {
    int i = blockIdx.x * blockDim.x + threadIdx.x;
    if (i < 1024 * 768) {
        int j = i / 768, k = i % 768;
        float v = (k < 512) ? Wih0[j * 512 + k] : Whh0[j * 256 + (k - 512)];
        split_bf16(v, d_W0h[i], d_W0l[i]);
    }
    if (i < 1024 * 512) {
        int j = i / 512, k = i % 512;
        float v = (k < 256) ? Wih1[j * 256 + k] : Whh1[j * 256 + (k - 256)];
        split_bf16(v, d_W1h[i], d_W1l[i]);
    }
    if (i < 1024) {
        d_b0[i] = bih0[i] + bhh0[i];
        d_b1[i] = bih1[i] + bhh1[i];
    }
}

// ---------------- zero-init state ----------------
__global__ void init_kernel(int B) {
    int i = blockIdx.x * blockDim.x + threadIdx.x;
    __nv_bfloat16 z = __float2bfloat16(0.f);
    if (i < B * 768) { d_X0h[i] = z; d_X0l[i] = z; }
    if (i < B * 512) { d_X1h[i] = z; d_X1l[i] = z; }
    if (i < B * 256) { d_c0[i] = 0.f; d_c1[i] = 0.f; d_q[i] = 0.f; }
}

// ---------------- attention + segment softmax + weighted readout ----------------
__global__ void attention_kernel(const float* __restrict__ nodes,
                                 float* __restrict__ dout, int final_iter) {
    int g = blockIdx.x;
    int s = d_starts[g], en = d_starts[g + 1];
    __shared__ float qs[256];
    __shared__ float red[8];
    __shared__ float s_max, s_inv;
    int tid = threadIdx.x, lane = tid & 31, w = tid >> 5;

    qs[tid] = d_q[(size_t)g * 256 + tid];
    __syncthreads();

    float lmax = -3.4e38f;
    for (int n = s + w; n < en; n += 8) {
        const float* row = nodes + (size_t)n * 256;
        float d = 0.f;
        #pragma unroll
        for (int k = 0; k < 8; k++) d = fmaf(row[lane + 32 * k], qs[lane + 32 * k], d);
        #pragma unroll
        for (int o = 16; o; o >>= 1) d += __shfl_xor_sync(0xffffffffu, d, o);
        if (lane == 0) d_e[n] = d;
        lmax = fmaxf(lmax, d);
    }
    if (lane == 0) red[w] = lmax;
    __syncthreads();
    if (tid == 0) {
        float m = red[0];
        #pragma unroll
        for (int i = 1; i < 8; i++) m = fmaxf(m, red[i]);
        s_max = m;
    }
    __syncthreads();
    float gm = s_max;

    float lsum = 0.f;
    for (int n = s + tid; n < en; n += 256) {
        float ex = expf(d_e[n] - gm);
        d_e[n] = ex;
        lsum += ex;
    }
    #pragma unroll
    for (int o = 16; o; o >>= 1) lsum += __shfl_xor_sync(0xffffffffu, lsum, o);
    if (lane == 0) red[w] = lsum;
    __syncthreads();
    if (tid == 0) {
        float sd = 0.f;
        #pragma unroll
        for (int i = 0; i < 8; i++) sd += red[i];
        s_inv = (sd > 0.f) ? 1.f / sd : 0.f;
    }
    __syncthreads();
    float inv = s_inv;

    float a0 = 0.f, a1 = 0.f, a2 = 0.f, a3 = 0.f;
    int n = s;
    for (; n + 3 < en; n += 4) {
        a0 = fmaf(d_e[n + 0], nodes[(size_t)(n + 0) * 256 + tid], a0);
        a1 = fmaf(d_e[n + 1], nodes[(size_t)(n + 1) * 256 + tid], a1);
        a2 = fmaf(d_e[n + 2], nodes[(size_t)(n + 2) * 256 + tid], a2);
        a3 = fmaf(d_e[n + 3], nodes[(size_t)(n + 3) * 256 + tid], a3);
    }
    for (; n < en; n++) a0 = fmaf(d_e[n], nodes[(size_t)n * 256 + tid], a0);
    float acc = ((a0 + a1) + (a2 + a3)) * inv;

    if (final_iter) {
        dout[(size_t)g * 512 + tid] = qs[tid];
        dout[(size_t)g * 512 + 256 + tid] = acc;
    } else {
        // write q_star as bf16 hi/lo into layer0 GEMM input
        __nv_bfloat16 h, l;
        split_bf16(qs[tid], h, l);
        d_X0h[(size_t)g * 768 + tid] = h;
        d_X0l[(size_t)g * 768 + tid] = l;
        split_bf16(acc, h, l);
        d_X0h[(size_t)g * 768 + 256 + tid] = h;
        d_X0l[(size_t)g * 768 + 256 + tid] = l;
    }
}

// ---------------- mma.sync bf16-split GEMM: gates[M,1024] = X[M,K] * W[1024,K]^T ----
// CTA tile 128x128, 8 warps (4m x 2n), warp tile 32x64, BK=32, 2-stage cp.async.
// smem per stage: 4 arrays (Ah, Al, Bh, Bl) of 128 rows x 40 bf16 (80B padded rows).
#define ROWB 80                    // padded row bytes (conflict-free ldmatrix)
#define ARR  (128 * ROWB)          // 10240 B per array
#define STG  (4 * ARR)             // 40960 B per stage
#define SMEM_GEMM (2 * STG)        // 81920 B

__global__ __launch_bounds__(256, 1) void mma_gates(int layer, int B) {
    const __nv_bfloat16* __restrict__ Agh = layer ? d_X1h : d_X0h;
    const __nv_bfloat16* __restrict__ Agl = layer ? d_X1l : d_X0l;
    const __nv_bfloat16* __restrict__ Wgh = layer ? d_W1h : d_W0h;
    const __nv_bfloat16* __restrict__ Wgl = layer ? d_W1l : d_W0l;
    const int K = layer ? 512 : 768;

    extern __shared__ __nv_bfloat16 sm[];
    const uint32_t sbase = smem_u32(sm);

    const int tid = threadIdx.x, lane = tid & 31, warp = tid >> 5;
    const int wm = warp >> 1, wn = warp & 1;
    const int tm = blockIdx.y, tn = blockIdx.x;

    float c[2][8][4];
    #pragma unroll
    for (int i = 0; i < 2; i++)
        #pragma unroll
        for (int j = 0; j < 8; j++)
            #pragma unroll
            for (int k = 0; k < 4; k++) c[i][j][k] = 0.f;

    // per-thread cp.async mapping: 2 x (row, 16B-chunk) covering 128x4 chunks
    int idx0 = tid, idx1 = tid + 256;
    int row0 = idx0 >> 2, ch0 = idx0 & 3;
    int row1 = idx1 >> 2, ch1 = idx1 & 3;
    int ar0 = tm * 128 + row0; if (ar0 >= B) ar0 = B - 1;
    int ar1 = tm * 128 + row1; if (ar1 >= B) ar1 = B - 1;
    int br0 = tn * 128 + row0;
    int br1 = tn * 128 + row1;

    const int niter = K >> 5;

    // issue chunk i into stage buffer
    #define ISSUE(I, BUF) do {                                                   \
        int _k0 = (I) << 5;                                                      \
        uint32_t _d0 = sbase + (BUF) * STG + row0 * ROWB + ch0 * 16;             \
        uint32_t _d1 = sbase + (BUF) * STG + row1 * ROWB + ch1 * 16;             \
        size_t _a0 = (size_t)ar0 * K + _k0 + ch0 * 8;                            \
        size_t _a1 = (size_t)ar1 * K + _k0 + ch1 * 8;                            \
        size_t _b0 = (size_t)br0 * K + _k0 + ch0 * 8;                            \
        size_t _b1 = (size_t)br1 * K + _k0 + ch1 * 8;                            \
        cp16(_d0 + 0 * ARR, Agh + _a0);  cp16(_d1 + 0 * ARR, Agh + _a1);         \
        cp16(_d0 + 1 * ARR, Agl + _a0);  cp16(_d1 + 1 * ARR, Agl + _a1);         \
        cp16(_d0 + 2 * ARR, Wgh + _b0);  cp16(_d1 + 2 * ARR, Wgh + _b1);         \
        cp16(_d0 + 3 * ARR, Wgl + _b0);  cp16(_d1 + 3 * ARR, Wgl + _b1);         \
        CP_COMMIT();                                                             \
    } while (0)

    ISSUE(0, 0);

    // ldmatrix per-lane address offsets
    const int m0 = wm * 32, n0 = wn * 64;
    const uint32_t a_row = m0 + (lane & 15);
    const uint32_t a_koff = (lane >> 4) * 16;                    // bytes
    const uint32_t b_row = n0 + (lane & 7) + ((lane >> 4) << 3);
    const uint32_t b_koff = ((lane >> 3) & 1) * 16;              // bytes

    for (int i = 0; i < niter; i++) {
        int buf = i & 1;
        if (i + 1 < niter) { ISSUE(i + 1, buf ^ 1); CP_WAIT1(); }
        else               { CP_WAIT0(); }
        __syncthreads();

        uint32_t sb = sbase + buf * STG;
        uint32_t aAh = sb + 0 * ARR, aAl = sb + 1 * ARR;
        uint32_t aBh = sb + 2 * ARR, aBl = sb + 3 * ARR;

        #pragma unroll
        for (int kk = 0; kk < 2; kk++) {
            uint32_t kb = kk * 32;   // bytes: 16 bf16
            uint32_t ah[2][4], al[2][4], bh[4][4], bl[4][4];
            ldsm4(ah[0], aAh + a_row * ROWB + kb + a_koff);
            ldsm4(ah[1], aAh + (a_row + 16) * ROWB + kb + a_koff);
            ldsm4(al[0], aAl + a_row * ROWB + kb + a_koff);
            ldsm4(al[1], aAl + (a_row + 16) * ROWB + kb + a_koff);
            #pragma unroll
            for (int nb = 0; nb < 4; nb++) {
                ldsm4(bh[nb], aBh + (b_row + nb * 16) * ROWB + kb + b_koff);
                ldsm4(bl[nb], aBl + (b_row + nb * 16) * ROWB + kb + b_koff);
            }
            #pragma unroll
            for (int mi = 0; mi < 2; mi++)
                #pragma unroll
                for (int nb = 0; nb < 4; nb++)
                    #pragma unroll
                    for (int h = 0; h < 2; h++) {
                        int n8 = nb * 2 + h;
                        mma16816(c[mi][n8], ah[mi], &bh[nb][h * 2]);   // hi*hi
                        mma16816(c[mi][n8], ah[mi], &bl[nb][h * 2]);   // hi*lo
                        mma16816(c[mi][n8], al[mi], &bh[nb][h * 2]);   // lo*hi
                    }
        }
        __syncthreads();
    }

    // epilogue: write fp32 gates
    int g = lane >> 2, qt = lane & 3;
    #pragma unroll
    for (int mi = 0; mi < 2; mi++) {
        #pragma unroll
        for (int n8 = 0; n8 < 8; n8++) {
            int row = tm * 128 + m0 + mi * 16 + g;
            int col = tn * 128 + n0 + n8 * 8 + qt * 2;
            if (row < B)
                *(float2*)&d_gates[(size_t)row * 1024 + col] = make_float2(c[mi][n8][0], c[mi][n8][1]);
            if (row + 8 < B)
                *(float2*)&d_gates[(size_t)(row + 8) * 1024 + col] = make_float2(c[mi][n8][2], c[mi][n8][3]);
        }
    }
    #undef ISSUE
}

// ---------------- LSTM pointwise: gates -> (h, c), writes bf16 split inputs ----
__global__ void lstm_act_kernel(int layer, int B) {
    int idx = blockIdx.x * blockDim.x + threadIdx.x;
    if (idx >= B * 256) return;
    int b = idx >> 8, t = idx & 255;
    const float* gr = d_gates + (size_t)b * 1024;
    const float* bs = (layer == 0) ? d_b0 : d_b1;
    float* c = (layer == 0) ? d_c0 : d_c1;

    float gi = gr[t]       + bs[t];
    float gf = gr[t + 256] + bs[t + 256];
    float gg = gr[t + 512] + bs[t + 512];
    float go = gr[t + 768] + bs[t + 768];

    float si = 1.f / (1.f + expf(-gi));
    float sf = 1.f / (1.f + expf(-gf));
    float tg = tanhf(gg);
    float so = 1.f / (1.f + expf(-go));

    float cn = sf * c[idx] + si * tg;
    c[idx] = cn;
    float hn = so * tanhf(cn);

    __nv_bfloat16 h, l;
    split_bf16(hn, h, l);
    if (layer == 0) {
        d_X0h[(size_t)b * 768 + 512 + t] = h;
        d_X0l[(size_t)b * 768 + 512 + t] = l;
        d_X1h[(size_t)b * 512 + t]       = h;
        d_X1l[(size_t)b * 512 + t]       = l;
    } else {
        d_X1h[(size_t)b * 512 + 256 + t] = h;
        d_X1l[(size_t)b * 512 + 256 + t] = l;
        d_q[idx] = hn;
    }
}

// ---------------- host launcher ----------------
extern "C" void kernel_launch(void* const* d_in, const int* in_sizes, int n_in,
                              void* d_out, int out_size) {
    const float* nodes = (const float*)d_in[0];
    const void*  gid   = d_in[1];
    int N = in_sizes[1];

    int wbase = (in_sizes[2] == 1) ? 3 : 2;
    const float* Wih0 = (const float*)d_in[wbase + 0];
    const float* Whh0 = (const float*)d_in[wbase + 1];
    const float* bih0 = (const float*)d_in[wbase + 2];
    const float* bhh0 = (const float*)d_in[wbase + 3];
    const float* Wih1 = (const float*)d_in[wbase + 4];
    const float* Whh1 = (const float*)d_in[wbase + 5];
    const float* bih1 = (const float*)d_in[wbase + 6];
    const float* bhh1 = (const float*)d_in[wbase + 7];

    int B = out_size / (2 * Hh);
    float* out = (float*)d_out;

    cudaFuncSetAttribute(mma_gates, cudaFuncAttributeMaxDynamicSharedMemorySize, SMEM_GEMM);

    detect_kernel<<<1, 1>>>((const int*)gid, N);
    starts_kernel<<<(B + 1 + 255) / 256, 256>>>(gid, N, B);
    pack_kernel<<<(1024 * 768 + 255) / 256, 256>>>(Wih0, Whh0, bih0, bhh0,
                                                   Wih1, Whh1, bih1, bhh1);
    init_kernel<<<(B * 768 + 255) / 256, 256>>>(B);

    dim3 gemm_grid(1024 / 128, (B + 127) / 128);
    const int M_ITERS = 6;
    for (int i = 0; i < M_ITERS; i++) {
        int final_iter = (i == M_ITERS - 1) ? 1 : 0;
        attention_kernel<<<B, 256>>>(nodes, out, final_iter);
        if (!final_iter) {
            mma_gates<<<gemm_grid, 256, SMEM_GEMM>>>(0, B);
            lstm_act_kernel<<<(B * 256 + 255) / 256, 256>>>(0, B);
            mma_gates<<<gemm_grid, 256, SMEM_GEMM>>>(1, B);
            lstm_act_kernel<<<(B * 256 + 255) / 256, 256>>>(1, B);
        }
    }
}